// round 2
// baseline (speedup 1.0000x reference)
#include <cuda_runtime.h>
#include <math.h>

// Problem constants (fixed by the dataset generator: N=1000, K=4, D=256, M=4)
#define NNODES 1000
#define KNB    4
#define NE     (NNODES*KNB)   // 4000 edges; paths[0:4000] enumerate them as (a, neigh[a][j]) at row a*4+j
#define D      256
#define NSTEP  3
#define PBLOCKS 296

// ---------------- scratch (static device memory; no runtime allocation) ----------------
__device__ __align__(16) float d_U[6*NNODES*D];     // U1/U2 per step: index (s*2+half)
__device__ __align__(16) float d_H[NSTEP*NE*D];     // relu(U1[a]+U2[b]+b1)
__device__ __align__(16) float d_G[NSTEP*NE*D];     // H @ Wc[s] + bc[s]   (== E @ Wa1_s)
__device__ __align__(16) float d_Wc[NSTEP*D*D];     // W2[s] @ Wa1[s*D:(s+1)*D, :]
__device__ __align__(16) float d_bc[NSTEP*D];       // b2[s] @ Wa1_s
__device__ __align__(16) float d_Wd[D*128];         // W2[0] @ Ws1
__device__ __align__(16) float d_bd[128];           // b2[0] @ Ws1 + bs1
__device__ __align__(16) float d_SC1[NE*128];       // relu(H0 @ Wd + bd)  (== relu(E0@Ws1+bs1))
__device__ __align__(16) float d_T[NE];             // sigmoid(SC1 @ Ws2 + bs2) per edge
__device__ __align__(16) int   d_nbr[NE];           // nbr[a*4+j] = neigh[a][j]
__device__ __align__(16) float d_partial[PBLOCKS*D];
__device__ __align__(16) float d_agg[D];

// ---------------- generic tiled SIMT GEMM: C = A(MxK) @ B(KxN) (+bias) (relu?) ----------------
#define BM 64
#define BN 64
#define BK 32

__global__ void gemm64(const float* __restrict__ A, const float* __restrict__ B,
                       const float* __restrict__ bias, float* __restrict__ C,
                       int M, int N, int K, int doRelu,
                       long sA, long sB, long sC, long sBias)
{
    A += (long)blockIdx.z * sA;
    B += (long)blockIdx.z * sB;
    C += (long)blockIdx.z * sC;
    const float* bptr = bias;
    if (bptr) bptr += (long)blockIdx.z * sBias;

    __shared__ __align__(16) float As[BM][36];   // padded: row stride 144B (16B multiple)
    __shared__ __align__(16) float Bs[BK][68];   // padded: row stride 272B

    int tid = threadIdx.x;
    int tx = tid & 15, ty = tid >> 4;
    int bx = blockIdx.x, by = blockIdx.y;

    int ar = tid >> 3, ac = (tid & 7) << 2;   // A tile loader coords
    int br = tid >> 4, bc = (tid & 15) << 2;  // B tile loader coords

    float acc[4][4];
#pragma unroll
    for (int i = 0; i < 4; i++)
#pragma unroll
        for (int j = 0; j < 4; j++) acc[i][j] = 0.f;

    for (int kt = 0; kt < K; kt += BK) {
#pragma unroll
        for (int rr = 0; rr < BM; rr += 32) {
            int gr = by*BM + ar + rr;
            float4 v = make_float4(0.f,0.f,0.f,0.f);
            if (gr < M) v = *(const float4*)(A + (long)gr*K + kt + ac);
            *(float4*)&As[ar+rr][ac] = v;
        }
#pragma unroll
        for (int rr = 0; rr < BK; rr += 16) {
            float4 v = *(const float4*)(B + (long)(kt+br+rr)*N + bx*BN + bc);
            *(float4*)&Bs[br+rr][bc] = v;
        }
        __syncthreads();
#pragma unroll
        for (int k = 0; k < BK; k++) {
            float a0 = As[ty*4+0][k];
            float a1 = As[ty*4+1][k];
            float a2 = As[ty*4+2][k];
            float a3 = As[ty*4+3][k];
            float4 b = *(const float4*)&Bs[k][tx*4];
            acc[0][0] = fmaf(a0,b.x,acc[0][0]); acc[0][1] = fmaf(a0,b.y,acc[0][1]);
            acc[0][2] = fmaf(a0,b.z,acc[0][2]); acc[0][3] = fmaf(a0,b.w,acc[0][3]);
            acc[1][0] = fmaf(a1,b.x,acc[1][0]); acc[1][1] = fmaf(a1,b.y,acc[1][1]);
            acc[1][2] = fmaf(a1,b.z,acc[1][2]); acc[1][3] = fmaf(a1,b.w,acc[1][3]);
            acc[2][0] = fmaf(a2,b.x,acc[2][0]); acc[2][1] = fmaf(a2,b.y,acc[2][1]);
            acc[2][2] = fmaf(a2,b.z,acc[2][2]); acc[2][3] = fmaf(a2,b.w,acc[2][3]);
            acc[3][0] = fmaf(a3,b.x,acc[3][0]); acc[3][1] = fmaf(a3,b.y,acc[3][1]);
            acc[3][2] = fmaf(a3,b.z,acc[3][2]); acc[3][3] = fmaf(a3,b.w,acc[3][3]);
        }
        __syncthreads();
    }

    int c0 = bx*BN + tx*4;
    float4 bv = make_float4(0.f,0.f,0.f,0.f);
    if (bptr) bv = *(const float4*)(bptr + c0);
#pragma unroll
    for (int i = 0; i < 4; i++) {
        int gr = by*BM + ty*4 + i;
        if (gr < M) {
            float4 o;
            o.x = acc[i][0] + bv.x; o.y = acc[i][1] + bv.y;
            o.z = acc[i][2] + bv.z; o.w = acc[i][3] + bv.w;
            if (doRelu) {
                o.x = fmaxf(o.x,0.f); o.y = fmaxf(o.y,0.f);
                o.z = fmaxf(o.z,0.f); o.w = fmaxf(o.w,0.f);
            }
            *(float4*)(C + (long)gr*N + c0) = o;
        }
    }
}

// ---------------- small kernels ----------------
__global__ void build_nbr(const int* __restrict__ paths, int* __restrict__ nbr)
{
    int i = blockIdx.x*blockDim.x + threadIdx.x;
    if (i < NE) nbr[i] = paths[i*4 + 1];   // paths row i = (i/4, neigh[i/4][i%4], ...)
}

// bc[s][n] = sum_e b2[s][e] * Wa1[s*D + e][n]   (one block per s, 256 threads)
__global__ void build_bc(const float* __restrict__ b2, const float* __restrict__ Wa1,
                         float* __restrict__ bc)
{
    int s = blockIdx.x, n = threadIdx.x;
    const float* Wrow = Wa1 + (long)s*D*D;
    float acc = 0.f;
#pragma unroll 8
    for (int e = 0; e < D; e++) acc = fmaf(b2[s*D + e], Wrow[(long)e*D + n], acc);
    bc[s*D + n] = acc;
}

// bd[n] = bs1[n] + sum_e b2[0][e] * Ws1[e][n]   (128 threads)
__global__ void build_bd(const float* __restrict__ b2, const float* __restrict__ Ws1,
                         const float* __restrict__ bs1, float* __restrict__ bd)
{
    int n = threadIdx.x;
    float acc = bs1[n];
#pragma unroll 8
    for (int e = 0; e < D; e++) acc = fmaf(b2[e], Ws1[e*128 + n], acc);
    bd[n] = acc;
}

// h[s][e][:] = relu(U1[s][src] + U2[s][dst] + b1[s]) ; one block per (s,e)
__global__ void build_h(const float* __restrict__ U, const float* __restrict__ b1,
                        const int* __restrict__ nbr, float* __restrict__ H)
{
    int se = blockIdx.x;
    int s = se / NE, e = se - s*NE;
    int src = e >> 2;
    int dst = nbr[e];
    int d = threadIdx.x;
    const float* u1 = U + ((long)(s*2+0)*NNODES + src)*D;
    const float* u2 = U + ((long)(s*2+1)*NNODES + dst)*D;
    float v = u1[d] + u2[d] + b1[s*D + d];
    H[(long)se*D + d] = fmaxf(v, 0.f);
}

// t[e] = sigmoid(SC1[e] . Ws2 + bs2) ; warp per edge
__global__ void score_t(const float* __restrict__ SC1, const float* __restrict__ Ws2,
                        const float* __restrict__ bs2, float* __restrict__ T)
{
    int e = blockIdx.x*8 + (threadIdx.x >> 5);
    int lane = threadIdx.x & 31;
    if (e >= NE) return;
    const float* r = SC1 + (long)e*128;
    float s = 0.f;
#pragma unroll
    for (int i = 0; i < 4; i++) s = fmaf(r[lane + 32*i], Ws2[lane + 32*i], s);
#pragma unroll
    for (int o = 16; o; o >>= 1) s += __shfl_xor_sync(0xFFFFFFFFu, s, o);
    if (lane == 0) T[e] = 1.f / (1.f + expf(-(s + bs2[0])));
}

__device__ __forceinline__ int edge_id(int a, int b, const int4* __restrict__ nbr4)
{
    int4 nb = nbr4[a];
    int j = 3;
    if (nb.x == b) j = 0;
    else if (nb.y == b) j = 1;
    else if (nb.z == b) j = 2;
    return (a << 2) | j;
}

// Per-path: sum valid G rows, +ba1, relu, accumulate; gather score. Warp per path.
__global__ void path_kernel(const int* __restrict__ paths, const int* __restrict__ plen,
                            const int* __restrict__ nbr, const float* __restrict__ G,
                            const float* __restrict__ T, const float* __restrict__ ba1,
                            float* __restrict__ scores, float* __restrict__ partial, int P)
{
    const int4* paths4 = (const int4*)paths;
    const int4* nbr4   = (const int4*)nbr;
    int lane = threadIdx.x & 31;
    int wib  = threadIdx.x >> 5;             // warp in block (0..7)
    int gw   = blockIdx.x*8 + wib;
    int nw   = gridDim.x*8;

    float bb[8], acc[8];
#pragma unroll
    for (int i = 0; i < 8; i++) { bb[i] = ba1[lane + 32*i]; acc[i] = 0.f; }

    for (int p = gw; p < P; p += nw) {
        int4 pr = paths4[p];
        int L = plen[p] - 1;                 // 1..3 valid steps

        float sum[8];
        int e0 = edge_id(pr.x, pr.y, nbr4);
        const float* g0 = G + (long)e0*D;
#pragma unroll
        for (int i = 0; i < 8; i++) sum[i] = g0[lane + 32*i];

        if (L > 1) {
            int e1 = edge_id(pr.y, pr.z, nbr4);
            const float* g1 = G + ((long)NE + e1)*D;
#pragma unroll
            for (int i = 0; i < 8; i++) sum[i] += g1[lane + 32*i];
        }
        if (L > 2) {
            int e2 = edge_id(pr.z, pr.w, nbr4);
            const float* g2 = G + ((long)2*NE + e2)*D;
#pragma unroll
            for (int i = 0; i < 8; i++) sum[i] += g2[lane + 32*i];
        }
#pragma unroll
        for (int i = 0; i < 8; i++) acc[i] += fmaxf(sum[i] + bb[i], 0.f);

        if (lane == 0) scores[p] = T[e0];
    }

    __shared__ float red[8][D];
#pragma unroll
    for (int i = 0; i < 8; i++) red[wib][lane + 32*i] = acc[i];
    __syncthreads();

    int d = threadIdx.x;                      // 0..255
    float s = 0.f;
#pragma unroll
    for (int w = 0; w < 8; w++) s += red[w][d];   // fixed order -> deterministic
    partial[(long)blockIdx.x*D + d] = s;
}

// aggregated[d] = (sum_p a1[p]) @ Wa2 + P*ba2
__global__ void finalize(const float* __restrict__ partial, int nblk,
                         const float* __restrict__ Wa2, const float* __restrict__ ba2,
                         int P, float* __restrict__ agg)
{
    __shared__ float S[D];
    int d = threadIdx.x;
    float s = 0.f;
    for (int b = 0; b < nblk; b++) s += partial[(long)b*D + d];   // fixed order
    S[d] = s;
    __syncthreads();
    float a = (float)P * ba2[d];
#pragma unroll 8
    for (int e = 0; e < D; e++) a = fmaf(S[e], Wa2[e*D + d], a);
    agg[d] = a;
}

__global__ void add_out(const float* __restrict__ nf, const float* __restrict__ agg,
                        float* __restrict__ out)
{
    int i = blockIdx.x*blockDim.x + threadIdx.x;
    if (i < NNODES*D) out[i] = nf[i] + agg[i & (D-1)];
}

// ---------------- launch ----------------
extern "C" void kernel_launch(void* const* d_in, const int* in_sizes, int n_in,
                              void* d_out, int out_size)
{
    const float* nf    = (const float*)d_in[0];
    const int*   paths = (const int*)  d_in[1];
    const int*   plen  = (const int*)  d_in[2];
    const float* W1    = (const float*)d_in[3];
    const float* b1    = (const float*)d_in[4];
    const float* W2    = (const float*)d_in[5];
    const float* b2    = (const float*)d_in[6];
    const float* Ws1   = (const float*)d_in[7];
    const float* bs1   = (const float*)d_in[8];
    const float* Ws2   = (const float*)d_in[9];
    const float* bs2   = (const float*)d_in[10];
    const float* Wa1   = (const float*)d_in[11];
    const float* ba1   = (const float*)d_in[12];
    const float* Wa2   = (const float*)d_in[13];
    const float* ba2   = (const float*)d_in[14];

    int P = in_sizes[2];                 // 84000 paths

    float* out     = (float*)d_out;
    float* updated = out;                // [1000*256]
    float* scores  = out + NNODES*D;     // [P]

    float *U,*H,*G,*WC,*BC,*WD,*BD,*SC1,*T,*PARTIAL,*AGG; int* NBR;
    cudaGetSymbolAddress((void**)&U,   d_U);
    cudaGetSymbolAddress((void**)&H,   d_H);
    cudaGetSymbolAddress((void**)&G,   d_G);
    cudaGetSymbolAddress((void**)&WC,  d_Wc);
    cudaGetSymbolAddress((void**)&BC,  d_bc);
    cudaGetSymbolAddress((void**)&WD,  d_Wd);
    cudaGetSymbolAddress((void**)&BD,  d_bd);
    cudaGetSymbolAddress((void**)&SC1, d_SC1);
    cudaGetSymbolAddress((void**)&T,   d_T);
    cudaGetSymbolAddress((void**)&NBR, d_nbr);
    cudaGetSymbolAddress((void**)&PARTIAL, d_partial);
    cudaGetSymbolAddress((void**)&AGG, d_agg);

    const long ED = (long)NE*D;          // 1,024,000

    // 1. neighbor table from first NE path rows
    build_nbr<<<(NE+255)/256, 256>>>(paths, NBR);

    // 2. U tables: z = s*2+half ; B = W1 + z*65536 (W1[s][:256] / W1[s][256:]) ; C = U + z*256000
    gemm64<<<dim3(D/64, (NNODES+63)/64, 6), 256>>>(
        nf, W1, nullptr, U, NNODES, D, D, 0,
        0L, 65536L, (long)NNODES*D, 0L);

    // 3. Folded weights: Wc[s] = W2[s] @ Wa1_s ; Wd = W2[0] @ Ws1  (+ bias folds)
    gemm64<<<dim3(D/64, D/64, 3), 256>>>(
        W2, Wa1, nullptr, WC, D, D, D, 0, 65536L, 65536L, 65536L, 0L);
    gemm64<<<dim3(128/64, D/64, 1), 256>>>(
        W2, Ws1, nullptr, WD, D, 128, D, 0, 0L, 0L, 0L, 0L);
    build_bc<<<NSTEP, D>>>(b2, Wa1, BC);
    build_bd<<<1, 128>>>(b2, Ws1, bs1, BD);

    // 4. H = relu(U1[a]+U2[b]+b1)
    build_h<<<NSTEP*NE, 256>>>(U, b1, NBR, H);

    // 5. G[s] = H[s] @ Wc[s] + bc[s]   (== E[s] @ Wa1_s)
    gemm64<<<dim3(D/64, (NE+63)/64, 3), 256>>>(
        H, WC, BC, G, NE, D, D, 0, ED, 65536L, ED, 256L);

    // 6. SC1 = relu(H0 @ Wd + bd)      (== relu(E0 @ Ws1 + bs1))
    gemm64<<<dim3(128/64, (NE+63)/64, 1), 256>>>(
        H, WD, BD, SC1, NE, 128, D, 1, 0L, 0L, 0L, 0L);

    // 7. per-edge sigmoid score table
    score_t<<<(NE+7)/8, 256>>>(SC1, Ws2, bs2, T);

    // 8. per-path gather + relu + deterministic partial reduction; score gather
    path_kernel<<<PBLOCKS, 256>>>(paths, plen, NBR, G, T, ba1, scores, PARTIAL, P);

    // 9. aggregated vector
    finalize<<<1, 256>>>(PARTIAL, PBLOCKS, Wa2, ba2, P, AGG);

    // 10. updated = nf + aggregated
    add_out<<<(NNODES*D+255)/256, 256>>>(nf, AGG, updated);
}

// round 11
// speedup vs baseline: 1.0422x; 1.0422x over previous
#include <cuda_runtime.h>
#include <math.h>

// Problem constants (fixed by the dataset generator: N=1000, K=4, D=256, M=4)
#define NNODES 1000
#define KNB    4
#define NE     (NNODES*KNB)   // 4000 edges; path row a*4+j = (a, neigh[a][j], ...)
#define D      256
#define NSTEP  3
#define PBLOCKS 148

// ---------------- scratch (static device memory; no runtime allocation) ----------------
__device__ __align__(16) float d_U[6*NNODES*D];     // U1/U2 per step: index (s*2+half)
__device__ __align__(16) float d_G[NSTEP*NE*D];     // relu-H @ Wc[s] + bc[s]
__device__ __align__(16) float d_Wc[NSTEP*D*D];     // W2[s] @ Wa1[s*D:(s+1)*D, :]
__device__ __align__(16) float d_bc[NSTEP*D];       // b2[s] @ Wa1_s
__device__ __align__(16) float d_Wd[D*128];         // W2[0] @ Ws1
__device__ __align__(16) float d_bd[128];           // b2[0] @ Ws1 + bs1
__device__ __align__(16) float d_SC1[NE*128];       // relu(H0 @ Wd + bd)
__device__ __align__(16) float d_T[NE];             // per-edge sigmoid score
__device__ __align__(16) int   d_nbr[NE];
__device__ __align__(16) float d_partial[PBLOCKS*D];

// ---------------- double-buffered 64x64x16 fp32 GEMM ----------------
#define BK  16
#define BMP 68   // padded row stride (272B = 16B multiple, keeps LDS128 aligned)

__device__ __forceinline__ void fma16(float acc[4][4], float4 a, float4 b)
{
    acc[0][0]=fmaf(a.x,b.x,acc[0][0]); acc[0][1]=fmaf(a.x,b.y,acc[0][1]);
    acc[0][2]=fmaf(a.x,b.z,acc[0][2]); acc[0][3]=fmaf(a.x,b.w,acc[0][3]);
    acc[1][0]=fmaf(a.y,b.x,acc[1][0]); acc[1][1]=fmaf(a.y,b.y,acc[1][1]);
    acc[1][2]=fmaf(a.y,b.z,acc[1][2]); acc[1][3]=fmaf(a.y,b.w,acc[1][3]);
    acc[2][0]=fmaf(a.z,b.x,acc[2][0]); acc[2][1]=fmaf(a.z,b.y,acc[2][1]);
    acc[2][2]=fmaf(a.z,b.z,acc[2][2]); acc[2][3]=fmaf(a.z,b.w,acc[2][3]);
    acc[3][0]=fmaf(a.w,b.x,acc[3][0]); acc[3][1]=fmaf(a.w,b.y,acc[3][1]);
    acc[3][2]=fmaf(a.w,b.z,acc[3][2]); acc[3][3]=fmaf(a.w,b.w,acc[3][3]);
}

__device__ __forceinline__ void epilogue(float acc[4][4], const float* bptr, float* C,
                                         int M, int N, int doRelu, int bx, int by,
                                         int tx, int ty)
{
    int c0 = bx*64 + tx*4;
    float4 bv = make_float4(0.f,0.f,0.f,0.f);
    if (bptr) bv = *(const float4*)(bptr + c0);
#pragma unroll
    for (int i = 0; i < 4; i++) {
        int gr = by*64 + ty*4 + i;
        if (gr < M) {
            float4 o;
            o.x = acc[i][0] + bv.x; o.y = acc[i][1] + bv.y;
            o.z = acc[i][2] + bv.z; o.w = acc[i][3] + bv.w;
            if (doRelu) {
                o.x = fmaxf(o.x,0.f); o.y = fmaxf(o.y,0.f);
                o.z = fmaxf(o.z,0.f); o.w = fmaxf(o.w,0.f);
            }
            *(float4*)(C + (long)gr*N + c0) = o;
        }
    }
}

// C = A(MxK) @ B(KxN) (+bias) (relu?), batched over blockIdx.z with strides
__global__ void __launch_bounds__(256) gemm_t(
    const float* __restrict__ A, const float* __restrict__ B,
    const float* __restrict__ bias, float* __restrict__ C,
    int M, int N, int K, int doRelu,
    long sA, long sB, long sC, long sBias)
{
    A += (long)blockIdx.z * sA;
    B += (long)blockIdx.z * sB;
    C += (long)blockIdx.z * sC;
    const float* bptr = bias ? bias + (long)blockIdx.z * sBias : (const float*)0;

    __shared__ __align__(16) float As[2][BK][BMP];
    __shared__ __align__(16) float Bs[2][BK][BMP];

    int tid = threadIdx.x;
    int tx = tid & 15, ty = tid >> 4;
    int am = tid >> 2, ak = (tid & 3) << 2;
    int bk = tid >> 4, bn = (tid & 15) << 2;

    int arow = blockIdx.y*64 + am;
    int acl  = arow < M ? arow : 0;
    const float* Aptr = A + (long)acl*K + ak;
    const float* Bptr = B + (long)bk*N + blockIdx.x*64 + bn;

    float4 av = *(const float4*)Aptr;
    float4 bv = *(const float4*)Bptr;
    As[0][ak+0][am]=av.x; As[0][ak+1][am]=av.y; As[0][ak+2][am]=av.z; As[0][ak+3][am]=av.w;
    *(float4*)&Bs[0][bk][bn] = bv;
    __syncthreads();

    float acc[4][4];
#pragma unroll
    for (int i=0;i<4;i++)
#pragma unroll
        for (int j=0;j<4;j++) acc[i][j]=0.f;

    int nt = K/BK, buf = 0;
    for (int kt = 0; kt < nt; kt++) {
        if (kt+1 < nt) {
            av = *(const float4*)(Aptr + (kt+1)*BK);
            bv = *(const float4*)(Bptr + (long)(kt+1)*BK*N);
        }
#pragma unroll
        for (int k = 0; k < BK; k++) {
            float4 a = *(const float4*)&As[buf][k][ty<<2];
            float4 b = *(const float4*)&Bs[buf][k][tx<<2];
            fma16(acc, a, b);
        }
        if (kt+1 < nt) {
            int nb = buf^1;
            As[nb][ak+0][am]=av.x; As[nb][ak+1][am]=av.y;
            As[nb][ak+2][am]=av.z; As[nb][ak+3][am]=av.w;
            *(float4*)&Bs[nb][bk][bn] = bv;
            __syncthreads();
            buf = nb;
        }
    }
    epilogue(acc, bptr, C, M, N, doRelu, blockIdx.x, blockIdx.y, tx, ty);
}

// Same GEMM but A-row e is built on the fly: relu(U1[e>>2] + U2[nbr[e]] + b1[s]).
// K = D fixed. blockIdx.z = s.
__global__ void __launch_bounds__(256) gemm_g(
    const float* __restrict__ U, const int* __restrict__ nbr,
    const float* __restrict__ b1, const float* __restrict__ B,
    const float* __restrict__ bias, float* __restrict__ C,
    int N, int doRelu, long sB, long sC, long sBias)
{
    int s = blockIdx.z;
    B += (long)s * sB;
    C += (long)s * sC;
    const float* bptr = bias ? bias + (long)s * sBias : (const float*)0;
    const float* U1  = U + (long)(2*s  )*NNODES*D;
    const float* U2  = U + (long)(2*s+1)*NNODES*D;
    const float* b1z = b1 + s*D;

    __shared__ __align__(16) float As[2][BK][BMP];
    __shared__ __align__(16) float Bs[2][BK][BMP];

    int tid = threadIdx.x;
    int tx = tid & 15, ty = tid >> 4;
    int am = tid >> 2, ak = (tid & 3) << 2;
    int bk = tid >> 4, bn = (tid & 15) << 2;

    int e  = blockIdx.y*64 + am;
    int ec = e < NE ? e : 0;
    const float* u1 = U1 + (long)(ec>>2)*D + ak;
    const float* u2 = U2 + (long)nbr[ec]*D + ak;
    const float* bp = b1z + ak;
    const float* Bptr = B + (long)bk*N + blockIdx.x*64 + bn;

    float4 x = *(const float4*)u1;
    float4 y = *(const float4*)u2;
    float4 z = *(const float4*)bp;
    float4 av;
    av.x = fmaxf(x.x+y.x+z.x,0.f); av.y = fmaxf(x.y+y.y+z.y,0.f);
    av.z = fmaxf(x.z+y.z+z.z,0.f); av.w = fmaxf(x.w+y.w+z.w,0.f);
    float4 bv = *(const float4*)Bptr;
    As[0][ak+0][am]=av.x; As[0][ak+1][am]=av.y; As[0][ak+2][am]=av.z; As[0][ak+3][am]=av.w;
    *(float4*)&Bs[0][bk][bn] = bv;
    __syncthreads();

    float acc[4][4];
#pragma unroll
    for (int i=0;i<4;i++)
#pragma unroll
        for (int j=0;j<4;j++) acc[i][j]=0.f;

    int nt = D/BK, buf = 0;
    for (int kt = 0; kt < nt; kt++) {
        if (kt+1 < nt) {
            int off = (kt+1)*BK;
            x = *(const float4*)(u1 + off);
            y = *(const float4*)(u2 + off);
            z = *(const float4*)(bp + off);
            av.x = fmaxf(x.x+y.x+z.x,0.f); av.y = fmaxf(x.y+y.y+z.y,0.f);
            av.z = fmaxf(x.z+y.z+z.z,0.f); av.w = fmaxf(x.w+y.w+z.w,0.f);
            bv = *(const float4*)(Bptr + (long)off*N);
        }
#pragma unroll
        for (int k = 0; k < BK; k++) {
            float4 a = *(const float4*)&As[buf][k][ty<<2];
            float4 b = *(const float4*)&Bs[buf][k][tx<<2];
            fma16(acc, a, b);
        }
        if (kt+1 < nt) {
            int nb = buf^1;
            As[nb][ak+0][am]=av.x; As[nb][ak+1][am]=av.y;
            As[nb][ak+2][am]=av.z; As[nb][ak+3][am]=av.w;
            *(float4*)&Bs[nb][bk][bn] = bv;
            __syncthreads();
            buf = nb;
        }
    }
    epilogue(acc, bptr, C, NE, N, doRelu, blockIdx.x, blockIdx.y, tx, ty);
}

// ---------------- prep: nbr table + bias folds (one launch) ----------------
__global__ void prep(const int* __restrict__ paths, int* __restrict__ nbr,
                     const float* __restrict__ b2, const float* __restrict__ Wa1,
                     const float* __restrict__ Ws1, const float* __restrict__ bs1,
                     float* __restrict__ bc, float* __restrict__ bd)
{
    int bb = blockIdx.x;
    if (bb < 16) {
        int i = bb*256 + threadIdx.x;
        if (i < NE) nbr[i] = paths[i*4 + 1];
    } else if (bb < 19) {
        int s = bb - 16, n = threadIdx.x;
        const float* Wrow = Wa1 + (long)s*D*D;
        float acc = 0.f;
#pragma unroll 8
        for (int e2 = 0; e2 < D; e2++) acc = fmaf(b2[s*D + e2], Wrow[(long)e2*D + n], acc);
        bc[s*D + n] = acc;
    } else {
        int n = threadIdx.x;
        if (n < 128) {
            float acc = bs1[n];
#pragma unroll 8
            for (int e2 = 0; e2 < D; e2++) acc = fmaf(b2[e2], Ws1[e2*128 + n], acc);
            bd[n] = acc;
        }
    }
}

// t[e] = sigmoid(SC1[e] . Ws2 + bs2) ; warp per edge
__global__ void score_t(const float* __restrict__ SC1, const float* __restrict__ Ws2,
                        const float* __restrict__ bs2, float* __restrict__ T)
{
    int e = blockIdx.x*8 + (threadIdx.x >> 5);
    int lane = threadIdx.x & 31;
    if (e >= NE) return;
    const float* r = SC1 + (long)e*128;
    float s = 0.f;
#pragma unroll
    for (int i = 0; i < 4; i++) s = fmaf(r[lane + 32*i], Ws2[lane + 32*i], s);
#pragma unroll
    for (int o = 16; o; o >>= 1) s += __shfl_xor_sync(0xFFFFFFFFu, s, o);
    if (lane == 0) T[e] = 1.f / (1.f + expf(-(s + bs2[0])));
}

// ---------------- paths via structural indexing; warp handles 16 consecutive paths ----------------
__global__ void path_kernel(const int* __restrict__ nbr, const float* __restrict__ G,
                            const float* __restrict__ T, const float* __restrict__ ba1,
                            float* __restrict__ scores, float* __restrict__ partial, int P)
{
    int lane = threadIdx.x & 31;
    int wib  = threadIdx.x >> 5;
    int gw   = blockIdx.x*8 + wib;
    int nw   = gridDim.x*8;

    const float* G0 = G;
    const float* G1 = G + (long)NE*D;
    const float* G2 = G + 2L*NE*D;

    float bb[8], acc[8];
#pragma unroll
    for (int i = 0; i < 8; i++) { bb[i] = ba1[lane + 32*i]; acc[i] = 0.f; }

    int nchunk = P >> 4;                       // 84000/16 = 5250 (region boundaries are 16-aligned)
    for (int ch = gw; ch < nchunk; ch += nw) {
        int p0 = ch << 4;
        if (p0 < NE) {
            // len-2 paths: path p IS edge p
#pragma unroll 4
            for (int t = 0; t < 16; t++) {
                int e0 = p0 + t;
                const float* g = G0 + (long)e0*D;
#pragma unroll
                for (int i = 0; i < 8; i++) acc[i] += fmaxf(g[lane+32*i] + bb[i], 0.f);
                if (lane == 0) scores[e0] = T[e0];
            }
        } else if (p0 < 5*NE) {
            // len-3: q = p-4000; e0 = q/4; e1 = 4*nbr[e0] + q%4
            int q0 = p0 - NE;
            for (int g4 = 0; g4 < 4; g4++) {
                int e0 = (q0 >> 2) + g4;
                const float* g0p = G0 + (long)e0*D;
                float s0[8];
#pragma unroll
                for (int i = 0; i < 8; i++) s0[i] = g0p[lane+32*i];
                int b = nbr[e0];
                float tv = T[e0];
#pragma unroll
                for (int j = 0; j < 4; j++) {
                    const float* g1p = G1 + (long)(b*4 + j)*D;
#pragma unroll
                    for (int i = 0; i < 8; i++)
                        acc[i] += fmaxf(s0[i] + g1p[lane+32*i] + bb[i], 0.f);
                    if (lane == 0) scores[p0 + g4*4 + j] = tv;
                }
            }
        } else {
            // len-4: r = p-20000; e0 = r/16; e1 = 4*nbr[e0]+(r/4)%4; e2 = 4*nbr[e1]+r%4
            int r0 = p0 - 5*NE;
            int e0 = r0 >> 4;
            const float* g0p = G0 + (long)e0*D;
            float s0[8];
#pragma unroll
            for (int i = 0; i < 8; i++) s0[i] = g0p[lane+32*i];
            int b = nbr[e0];
            float tv = T[e0];
            for (int j = 0; j < 4; j++) {
                int e1 = b*4 + j;
                const float* g1p = G1 + (long)e1*D;
                float s1[8];
#pragma unroll
                for (int i = 0; i < 8; i++) s1[i] = s0[i] + g1p[lane+32*i];
                int c = nbr[e1];
#pragma unroll
                for (int i2 = 0; i2 < 4; i2++) {
                    const float* g2p = G2 + (long)(c*4 + i2)*D;
#pragma unroll
                    for (int i = 0; i < 8; i++)
                        acc[i] += fmaxf(s1[i] + g2p[lane+32*i] + bb[i], 0.f);
                    if (lane == 0) scores[p0 + j*4 + i2] = tv;
                }
            }
        }
    }

    __shared__ float red[8][D];
#pragma unroll
    for (int i = 0; i < 8; i++) red[wib][lane + 32*i] = acc[i];
    __syncthreads();

    int d = threadIdx.x;
    float s = 0.f;
#pragma unroll
    for (int w = 0; w < 8; w++) s += red[w][d];     // fixed order -> deterministic
    partial[(long)blockIdx.x*D + d] = s;
}

// Merged finalize + add_out: every block recomputes the identical aggregated
// vector (fixed-order sums -> bit-identical across blocks, deterministic),
// then writes its share of updated = nf + agg.
__global__ void __launch_bounds__(256) finalize_add(
    const float* __restrict__ partial, const float* __restrict__ Wa2,
    const float* __restrict__ ba2, int P,
    const float* __restrict__ nf, float* __restrict__ out)
{
    __shared__ float S[D];
    __shared__ float A[D];
    int d = threadIdx.x;
    float s = 0.f;
#pragma unroll 4
    for (int b = 0; b < PBLOCKS; b++) s += partial[(long)b*D + d];   // fixed order
    S[d] = s;
    __syncthreads();
    float a = (float)P * ba2[d];
#pragma unroll 8
    for (int e = 0; e < D; e++) a = fmaf(S[e], Wa2[e*D + d], a);
    A[d] = a;
    __syncthreads();
    for (int n = blockIdx.x; n < NNODES; n += gridDim.x)
        out[(long)n*D + d] = nf[(long)n*D + d] + A[d];
}

// ---------------- launch ----------------
extern "C" void kernel_launch(void* const* d_in, const int* in_sizes, int n_in,
                              void* d_out, int out_size)
{
    const float* nf    = (const float*)d_in[0];
    const int*   paths = (const int*)  d_in[1];
    const float* W1    = (const float*)d_in[3];
    const float* b1    = (const float*)d_in[4];
    const float* W2    = (const float*)d_in[5];
    const float* b2    = (const float*)d_in[6];
    const float* Ws1   = (const float*)d_in[7];
    const float* bs1   = (const float*)d_in[8];
    const float* Ws2   = (const float*)d_in[9];
    const float* bs2   = (const float*)d_in[10];
    const float* Wa1   = (const float*)d_in[11];
    const float* ba1   = (const float*)d_in[12];
    const float* Wa2   = (const float*)d_in[13];
    const float* ba2   = (const float*)d_in[14];

    int P = in_sizes[2];                 // 84000 paths

    float* out     = (float*)d_out;
    float* updated = out;                // [1000*256]
    float* scores  = out + NNODES*D;     // [P]

    float *U,*G,*WC,*BC,*WD,*BD,*SC1,*T,*PARTIAL; int* NBR;
    cudaGetSymbolAddress((void**)&U,   d_U);
    cudaGetSymbolAddress((void**)&G,   d_G);
    cudaGetSymbolAddress((void**)&WC,  d_Wc);
    cudaGetSymbolAddress((void**)&BC,  d_bc);
    cudaGetSymbolAddress((void**)&WD,  d_Wd);
    cudaGetSymbolAddress((void**)&BD,  d_bd);
    cudaGetSymbolAddress((void**)&SC1, d_SC1);
    cudaGetSymbolAddress((void**)&T,   d_T);
    cudaGetSymbolAddress((void**)&NBR, d_nbr);
    cudaGetSymbolAddress((void**)&PARTIAL, d_partial);

    const long ED = (long)NE*D;          // 1,024,000

    // 1. nbr table + bias folds (independent of everything downstream of it)
    prep<<<20, 256>>>(paths, NBR, b2, Wa1, Ws1, bs1, BC, BD);

    // 2. U tables: z = s*2+half ; B = W1 + z*65536 ; C = U + z*256000
    gemm_t<<<dim3(4, 16, 6), 256>>>(nf, W1, nullptr, U, NNODES, D, D, 0,
                                    0L, 65536L, (long)NNODES*D, 0L);

    // 3. Folded weights: Wc[s] = W2[s] @ Wa1_s ; Wd = W2[0] @ Ws1
    gemm_t<<<dim3(4, 4, 3), 256>>>(W2, Wa1, nullptr, WC, D, D, D, 0,
                                   65536L, 65536L, 65536L, 0L);
    gemm_t<<<dim3(2, 4, 1), 256>>>(W2, Ws1, nullptr, WD, D, 128, D, 0,
                                   0L, 0L, 0L, 0L);

    // 4. G[s] = relu(U1+U2+b1)[edges] @ Wc[s] + bc[s]   (H built in the loader)
    gemm_g<<<dim3(4, 63, 3), 256>>>(U, NBR, b1, WC, BC, G, D, 0,
                                    65536L, ED, 256L);

    // 5. SC1 = relu( relu-H0 @ Wd + bd )
    gemm_g<<<dim3(2, 63, 1), 256>>>(U, NBR, b1, WD, BD, SC1, 128, 1,
                                    0L, 0L, 0L);

    // 6. per-edge sigmoid score table
    score_t<<<500, 256>>>(SC1, Ws2, bs2, T);

    // 7. per-path structural gather + relu + deterministic partial reduction
    path_kernel<<<PBLOCKS, 256>>>(NBR, G, T, ba1, scores, PARTIAL, P);

    // 8. aggregated vector + output add (merged)
    finalize_add<<<PBLOCKS, 256>>>(PARTIAL, Wa2, ba2, P, nf, updated);
}

// round 14
// speedup vs baseline: 1.3807x; 1.3249x over previous
#include <cuda_runtime.h>
#include <math.h>

// Problem constants (fixed by generator: N=1000, K=4, D=256, M=4)
#define NNODES 1000
#define KNB    4
#define NE     (NNODES*KNB)
#define D      256
#define NSTEP  3
#define PBLOCKS 148

typedef unsigned long long u64;

// ---------------- scratch ----------------
__device__ __align__(16) float d_U[6*NNODES*D];
__device__ __align__(16) float d_G[NSTEP*NE*D];
__device__ __align__(16) float d_Wc[NSTEP*D*D];
__device__ __align__(16) float d_bc[NSTEP*D];
__device__ __align__(16) float d_Wd[D*128];
__device__ __align__(16) float d_bd[128];
__device__ __align__(16) float d_SC1[NE*128];
__device__ __align__(16) float d_T[NE];
__device__ __align__(16) int   d_nbr[NE];
__device__ __align__(16) float d_partial[PBLOCKS*D];

// ---------------- f32x2 packed math (sm_103a; PTX-only) ----------------
__device__ __forceinline__ u64 pack2s(float v)
{ u64 r; asm("mov.b64 %0, {%1, %1};" : "=l"(r) : "f"(v)); return r; }

__device__ __forceinline__ void fma2(u64& acc, u64 a, u64 b)
{ asm("fma.rn.f32x2 %0, %1, %2, %3;" : "=l"(acc) : "l"(a), "l"(b), "l"(acc)); }

__device__ __forceinline__ float2 unpack2(u64 v)
{ float lo, hi; asm("mov.b64 {%0, %1}, %2;" : "=f"(lo), "=f"(hi) : "l"(v)); return make_float2(lo, hi); }

// ---------------- 64x64x16 double-buffered GEMM core (f32x2 inner) ----------------
#define BK  16
#define BMP 68   // padded row stride (272B, 16B multiple)

__device__ __forceinline__ void fma2x8(u64 acc[4][2], float4 a, u64 b0, u64 b1)
{
    u64 a0 = pack2s(a.x), a1 = pack2s(a.y), a2 = pack2s(a.z), a3 = pack2s(a.w);
    fma2(acc[0][0], a0, b0); fma2(acc[0][1], a0, b1);
    fma2(acc[1][0], a1, b0); fma2(acc[1][1], a1, b1);
    fma2(acc[2][0], a2, b0); fma2(acc[2][1], a2, b1);
    fma2(acc[3][0], a3, b0); fma2(acc[3][1], a3, b1);
}

__device__ __forceinline__ void gemm_epilogue(u64 acc[4][2], const float* bptr,
                                              float* C, int M, int N, int doRelu,
                                              int bx, int by, int tx, int ty)
{
    int c0 = bx*64 + tx*4;
    float4 bv = make_float4(0.f,0.f,0.f,0.f);
    if (bptr) bv = *(const float4*)(bptr + c0);
#pragma unroll
    for (int i = 0; i < 4; i++) {
        int gr = by*64 + ty*4 + i;
        if (gr < M) {
            float2 lo = unpack2(acc[i][0]);
            float2 hi = unpack2(acc[i][1]);
            float4 o;
            o.x = lo.x + bv.x; o.y = lo.y + bv.y;
            o.z = hi.x + bv.z; o.w = hi.y + bv.w;
            if (doRelu) {
                o.x = fmaxf(o.x,0.f); o.y = fmaxf(o.y,0.f);
                o.z = fmaxf(o.z,0.f); o.w = fmaxf(o.w,0.f);
            }
            *(float4*)(C + (long)gr*N + c0) = o;
        }
    }
}

// Generic C = A@B (+bias)(relu), one 64x64 tile at (bx,by). Shared passed in.
__device__ __forceinline__ void gemm_core(
    float (*As)[BK][BMP], float (*Bs)[BK][BMP],
    const float* __restrict__ A, const float* __restrict__ B,
    const float* __restrict__ bptr, float* __restrict__ C,
    int M, int N, int K, int doRelu, int bx, int by)
{
    int tid = threadIdx.x;
    int tx = tid & 15, ty = tid >> 4;
    int am = tid >> 2, ak = (tid & 3) << 2;
    int bk = tid >> 4, bn = (tid & 15) << 2;

    int arow = by*64 + am;
    int acl  = arow < M ? arow : 0;
    const float* Aptr = A + (long)acl*K + ak;
    const float* Bptr = B + (long)bk*N + bx*64 + bn;

    float4 av = *(const float4*)Aptr;
    float4 bv = *(const float4*)Bptr;
    As[0][ak+0][am]=av.x; As[0][ak+1][am]=av.y; As[0][ak+2][am]=av.z; As[0][ak+3][am]=av.w;
    *(float4*)&Bs[0][bk][bn] = bv;
    __syncthreads();

    u64 acc[4][2] = {{0ull,0ull},{0ull,0ull},{0ull,0ull},{0ull,0ull}};

    int nt = K/BK, buf = 0;
    for (int kt = 0; kt < nt; kt++) {
        if (kt+1 < nt) {
            av = *(const float4*)(Aptr + (kt+1)*BK);
            bv = *(const float4*)(Bptr + (long)(kt+1)*BK*N);
        }
#pragma unroll
        for (int k = 0; k < BK; k++) {
            float4 a = *(const float4*)&As[buf][k][ty<<2];
            const u64* bp = (const u64*)&Bs[buf][k][tx<<2];
            fma2x8(acc, a, bp[0], bp[1]);
        }
        if (kt+1 < nt) {
            int nb = buf^1;
            As[nb][ak+0][am]=av.x; As[nb][ak+1][am]=av.y;
            As[nb][ak+2][am]=av.z; As[nb][ak+3][am]=av.w;
            *(float4*)&Bs[nb][bk][bn] = bv;
            __syncthreads();
            buf = nb;
        }
    }
    gemm_epilogue(acc, bptr, C, M, N, doRelu, bx, by, tx, ty);
}

// ---------------- launch 1: mega_pre (U gemm + Wc fold + Wd fold + prep) ----------------
// blocks: [0,384) U gemm; [384,432) Wc fold; [432,440) Wd fold; [440,460) prep
__global__ void __launch_bounds__(256) mega_pre(
    const float* __restrict__ nf, const float* __restrict__ W1, float* __restrict__ U,
    const float* __restrict__ W2, const float* __restrict__ Wa1, float* __restrict__ Wc,
    const float* __restrict__ Ws1, float* __restrict__ Wd,
    const int* __restrict__ paths, int* __restrict__ nbr,
    const float* __restrict__ b2, const float* __restrict__ bs1,
    float* __restrict__ bc, float* __restrict__ bd)
{
    __shared__ float As[2][BK][BMP];
    __shared__ float Bs[2][BK][BMP];
    int bb = blockIdx.x;
    if (bb < 384) {
        int z = bb >> 6, rem = bb & 63;
        int by = rem >> 2, bx = rem & 3;
        gemm_core(As, Bs, nf, W1 + (long)z*65536, (const float*)0,
                  U + (long)z*NNODES*D, NNODES, D, D, 0, bx, by);
    } else if (bb < 432) {
        int t = bb - 384;
        int z = t >> 4, rem = t & 15, by = rem >> 2, bx = rem & 3;
        gemm_core(As, Bs, W2 + (long)z*65536, Wa1 + (long)z*65536, (const float*)0,
                  Wc + (long)z*65536, D, D, D, 0, bx, by);
    } else if (bb < 440) {
        int t = bb - 432;
        int by = t >> 1, bx = t & 1;
        gemm_core(As, Bs, W2, Ws1, (const float*)0, Wd, D, 128, D, 0, bx, by);
    } else {
        int t = bb - 440;
        if (t < 16) {
            int i = t*256 + threadIdx.x;
            if (i < NE) nbr[i] = paths[i*4 + 1];
        } else if (t < 19) {
            int s = t - 16, n = threadIdx.x;
            const float* Wrow = Wa1 + (long)s*D*D;
            float acc = 0.f;
#pragma unroll 8
            for (int e2 = 0; e2 < D; e2++) acc = fmaf(b2[s*D + e2], Wrow[(long)e2*D + n], acc);
            bc[s*D + n] = acc;
        } else {
            int n = threadIdx.x;
            if (n < 128) {
                float acc = bs1[n];
#pragma unroll 8
                for (int e2 = 0; e2 < D; e2++) acc = fmaf(b2[e2], Ws1[e2*128 + n], acc);
                bd[n] = acc;
            }
        }
    }
}

// ---------------- launch 2: gemm_g2 — G (z<3) + SC1 (z==3), fused relu-H loader ----------------
__global__ void __launch_bounds__(256) gemm_g2(
    const float* __restrict__ U, const int* __restrict__ nbr,
    const float* __restrict__ b1,
    const float* __restrict__ Wc, const float* __restrict__ bc, float* __restrict__ G,
    const float* __restrict__ Wd, const float* __restrict__ bd, float* __restrict__ SC1)
{
    __shared__ float As[2][BK][BMP];
    __shared__ float Bs[2][BK][BMP];
    int z = blockIdx.z;
    const float *B, *bptr; float* C; int N, doRelu, s;
    if (z < 3) {
        s = z; N = D; B = Wc + (long)z*65536; bptr = bc + z*D;
        C = G + (long)z*NE*D; doRelu = 0;
    } else {
        if (blockIdx.x >= 2) return;
        s = 0; N = 128; B = Wd; bptr = bd; C = SC1; doRelu = 1;
    }
    const float* U1  = U + (long)(2*s  )*NNODES*D;
    const float* U2  = U + (long)(2*s+1)*NNODES*D;
    const float* b1z = b1 + s*D;

    int tid = threadIdx.x;
    int tx = tid & 15, ty = tid >> 4;
    int am = tid >> 2, ak = (tid & 3) << 2;
    int bk = tid >> 4, bn = (tid & 15) << 2;
    int bx = blockIdx.x, by = blockIdx.y;

    int e  = by*64 + am;
    int ec = e < NE ? e : 0;
    const float* u1 = U1 + (long)(ec>>2)*D + ak;
    const float* u2 = U2 + (long)nbr[ec]*D + ak;
    const float* bp = b1z + ak;
    const float* Bptr = B + (long)bk*N + bx*64 + bn;

    float4 x = *(const float4*)u1;
    float4 y = *(const float4*)u2;
    float4 zz = *(const float4*)bp;
    float4 av;
    av.x = fmaxf(x.x+y.x+zz.x,0.f); av.y = fmaxf(x.y+y.y+zz.y,0.f);
    av.z = fmaxf(x.z+y.z+zz.z,0.f); av.w = fmaxf(x.w+y.w+zz.w,0.f);
    float4 bv = *(const float4*)Bptr;
    As[0][ak+0][am]=av.x; As[0][ak+1][am]=av.y; As[0][ak+2][am]=av.z; As[0][ak+3][am]=av.w;
    *(float4*)&Bs[0][bk][bn] = bv;
    __syncthreads();

    u64 acc[4][2] = {{0ull,0ull},{0ull,0ull},{0ull,0ull},{0ull,0ull}};

    int nt = D/BK, buf = 0;
    for (int kt = 0; kt < nt; kt++) {
        if (kt+1 < nt) {
            int off = (kt+1)*BK;
            x  = *(const float4*)(u1 + off);
            y  = *(const float4*)(u2 + off);
            zz = *(const float4*)(bp + off);
            av.x = fmaxf(x.x+y.x+zz.x,0.f); av.y = fmaxf(x.y+y.y+zz.y,0.f);
            av.z = fmaxf(x.z+y.z+zz.z,0.f); av.w = fmaxf(x.w+y.w+zz.w,0.f);
            bv = *(const float4*)(Bptr + (long)off*N);
        }
#pragma unroll
        for (int k = 0; k < BK; k++) {
            float4 a = *(const float4*)&As[buf][k][ty<<2];
            const u64* bpp = (const u64*)&Bs[buf][k][tx<<2];
            fma2x8(acc, a, bpp[0], bpp[1]);
        }
        if (kt+1 < nt) {
            int nb = buf^1;
            As[nb][ak+0][am]=av.x; As[nb][ak+1][am]=av.y;
            As[nb][ak+2][am]=av.z; As[nb][ak+3][am]=av.w;
            *(float4*)&Bs[nb][bk][bn] = bv;
            __syncthreads();
            buf = nb;
        }
    }
    gemm_epilogue(acc, bptr, C, NE, N, doRelu, bx, by, tx, ty);
}

// ---------------- launch 3: per-edge sigmoid score ----------------
__global__ void score_t(const float* __restrict__ SC1, const float* __restrict__ Ws2,
                        const float* __restrict__ bs2, float* __restrict__ T)
{
    int e = blockIdx.x*8 + (threadIdx.x >> 5);
    int lane = threadIdx.x & 31;
    if (e >= NE) return;
    const float* r = SC1 + (long)e*128;
    float s = 0.f;
#pragma unroll
    for (int i = 0; i < 4; i++) s = fmaf(r[lane + 32*i], Ws2[lane + 32*i], s);
#pragma unroll
    for (int o = 16; o; o >>= 1) s += __shfl_xor_sync(0xFFFFFFFFu, s, o);
    if (lane == 0) T[e] = 1.f / (1.f + expf(-(s + bs2[0])));
}

// ---------------- launch 4: structural path gather ----------------
__global__ void path_kernel(const int* __restrict__ nbr, const float* __restrict__ G,
                            const float* __restrict__ T, const float* __restrict__ ba1,
                            float* __restrict__ scores, float* __restrict__ partial, int P)
{
    int lane = threadIdx.x & 31;
    int wib  = threadIdx.x >> 5;
    int gw   = blockIdx.x*8 + wib;
    int nw   = gridDim.x*8;

    const float* G0 = G;
    const float* G1 = G + (long)NE*D;
    const float* G2 = G + 2L*NE*D;

    float bb[8], acc[8];
#pragma unroll
    for (int i = 0; i < 8; i++) { bb[i] = ba1[lane + 32*i]; acc[i] = 0.f; }

    int nchunk = P >> 4;
    for (int ch = gw; ch < nchunk; ch += nw) {
        int p0 = ch << 4;
        if (p0 < NE) {
#pragma unroll 4
            for (int t = 0; t < 16; t++) {
                int e0 = p0 + t;
                const float* g = G0 + (long)e0*D;
#pragma unroll
                for (int i = 0; i < 8; i++) acc[i] += fmaxf(g[lane+32*i] + bb[i], 0.f);
                if (lane == 0) scores[e0] = T[e0];
            }
        } else if (p0 < 5*NE) {
            int q0 = p0 - NE;
            for (int g4 = 0; g4 < 4; g4++) {
                int e0 = (q0 >> 2) + g4;
                const float* g0p = G0 + (long)e0*D;
                float s0[8];
#pragma unroll
                for (int i = 0; i < 8; i++) s0[i] = g0p[lane+32*i];
                int b = nbr[e0];
                float tv = T[e0];
#pragma unroll
                for (int j = 0; j < 4; j++) {
                    const float* g1p = G1 + (long)(b*4 + j)*D;
#pragma unroll
                    for (int i = 0; i < 8; i++)
                        acc[i] += fmaxf(s0[i] + g1p[lane+32*i] + bb[i], 0.f);
                    if (lane == 0) scores[p0 + g4*4 + j] = tv;
                }
            }
        } else {
            int r0 = p0 - 5*NE;
            int e0 = r0 >> 4;
            const float* g0p = G0 + (long)e0*D;
            float s0[8];
#pragma unroll
            for (int i = 0; i < 8; i++) s0[i] = g0p[lane+32*i];
            int b = nbr[e0];
            float tv = T[e0];
            for (int j = 0; j < 4; j++) {
                int e1 = b*4 + j;
                const float* g1p = G1 + (long)e1*D;
                float s1[8];
#pragma unroll
                for (int i = 0; i < 8; i++) s1[i] = s0[i] + g1p[lane+32*i];
                int c = nbr[e1];
#pragma unroll
                for (int i2 = 0; i2 < 4; i2++) {
                    const float* g2p = G2 + (long)(c*4 + i2)*D;
#pragma unroll
                    for (int i = 0; i < 8; i++)
                        acc[i] += fmaxf(s1[i] + g2p[lane+32*i] + bb[i], 0.f);
                    if (lane == 0) scores[p0 + j*4 + i2] = tv;
                }
            }
        }
    }

    __shared__ float red[8][D];
#pragma unroll
    for (int i = 0; i < 8; i++) red[wib][lane + 32*i] = acc[i];
    __syncthreads();

    int d = threadIdx.x;
    float s = 0.f;
#pragma unroll
    for (int w = 0; w < 8; w++) s += red[w][d];     // fixed order -> deterministic
    partial[(long)blockIdx.x*D + d] = s;
}

// ---------------- launch 5: finalize + output add (merged) ----------------
__global__ void __launch_bounds__(256) finalize_add(
    const float* __restrict__ partial, const float* __restrict__ Wa2,
    const float* __restrict__ ba2, int P,
    const float* __restrict__ nf, float* __restrict__ out)
{
    __shared__ float S[D];
    __shared__ float A[D];
    int d = threadIdx.x;
    float s = 0.f;
#pragma unroll 4
    for (int b = 0; b < PBLOCKS; b++) s += partial[(long)b*D + d];   // fixed order
    S[d] = s;
    __syncthreads();
    float a = (float)P * ba2[d];
#pragma unroll 8
    for (int e = 0; e < D; e++) a = fmaf(S[e], Wa2[e*D + d], a);
    A[d] = a;
    __syncthreads();
    for (int n = blockIdx.x; n < NNODES; n += gridDim.x)
        out[(long)n*D + d] = nf[(long)n*D + d] + A[d];
}

// ---------------- launch ----------------
extern "C" void kernel_launch(void* const* d_in, const int* in_sizes, int n_in,
                              void* d_out, int out_size)
{
    const float* nf    = (const float*)d_in[0];
    const int*   paths = (const int*)  d_in[1];
    const float* W1    = (const float*)d_in[3];
    const float* b1    = (const float*)d_in[4];
    const float* W2    = (const float*)d_in[5];
    const float* b2    = (const float*)d_in[6];
    const float* Ws1   = (const float*)d_in[7];
    const float* bs1   = (const float*)d_in[8];
    const float* Ws2   = (const float*)d_in[9];
    const float* bs2   = (const float*)d_in[10];
    const float* Wa1   = (const float*)d_in[11];
    const float* ba1   = (const float*)d_in[12];
    const float* Wa2   = (const float*)d_in[13];
    const float* ba2   = (const float*)d_in[14];

    int P = in_sizes[2];                 // 84000 paths

    float* out     = (float*)d_out;
    float* updated = out;                // [1000*256]
    float* scores  = out + NNODES*D;     // [P]

    float *U,*G,*WC,*BC,*WD,*BD,*SC1,*T,*PARTIAL; int* NBR;
    cudaGetSymbolAddress((void**)&U,   d_U);
    cudaGetSymbolAddress((void**)&G,   d_G);
    cudaGetSymbolAddress((void**)&WC,  d_Wc);
    cudaGetSymbolAddress((void**)&BC,  d_bc);
    cudaGetSymbolAddress((void**)&WD,  d_Wd);
    cudaGetSymbolAddress((void**)&BD,  d_bd);
    cudaGetSymbolAddress((void**)&SC1, d_SC1);
    cudaGetSymbolAddress((void**)&T,   d_T);
    cudaGetSymbolAddress((void**)&NBR, d_nbr);
    cudaGetSymbolAddress((void**)&PARTIAL, d_partial);

    // 1. ALL independent pre-work in one chip-filling launch:
    //    U tables (384 blocks) + Wc fold (48) + Wd fold (8) + nbr/bias prep (20)
    mega_pre<<<460, 256>>>(nf, W1, U, W2, Wa1, WC, Ws1, WD,
                           paths, NBR, b2, bs1, BC, BD);

    // 2. G (z=0..2) + SC1 (z=3) in one launch; relu-H built in the A-loader
    gemm_g2<<<dim3(4, 63, 4), 256>>>(U, NBR, b1, WC, BC, G, WD, BD, SC1);

    // 3. per-edge sigmoid score table
    score_t<<<500, 256>>>(SC1, Ws2, bs2, T);

    // 4. per-path structural gather + deterministic partial reduction
    path_kernel<<<PBLOCKS, 256>>>(NBR, G, T, ba1, scores, PARTIAL, P);

    // 5. aggregated vector + output add (merged)
    finalize_add<<<PBLOCKS, 256>>>(PARTIAL, Wa2, ba2, P, nf, updated);
}